// round 1
// baseline (speedup 1.0000x reference)
#include <cuda_runtime.h>

// Problem shape (fixed by setup_inputs): x [B, T, C] fp32, weight [C] fp32.
#define BB 8
#define TT 8192
#define CC 512
#define EPSF 1e-5f

// Scratch (device globals — no allocation allowed in kernel_launch).
__device__ float g_S1[BB * TT];
__device__ float g_Q[BB * TT];
__device__ float g_mean[BB * TT];
__device__ float g_inv[BB * TT];

// ---------------------------------------------------------------------------
// Stage A: per-frame reductions. One warp per frame (C=512 floats = 4 float4
// per lane). Produces S1[f] = sum_c x, Q[f] = sum_c x^2.
// ---------------------------------------------------------------------------
__global__ void __launch_bounds__(256) stageA(const float* __restrict__ x) {
    const int gwarp = (blockIdx.x * blockDim.x + threadIdx.x) >> 5;  // frame id
    const int lane = threadIdx.x & 31;

    const float4* p = reinterpret_cast<const float4*>(x + (size_t)gwarp * CC);
    float s = 0.f, q = 0.f;
#pragma unroll
    for (int k = 0; k < 4; k++) {
        float4 v = p[lane + k * 32];
        s += (v.x + v.y) + (v.z + v.w);
        q += v.x * v.x + v.y * v.y + v.z * v.z + v.w * v.w;
    }
#pragma unroll
    for (int o = 16; o > 0; o >>= 1) {
        s += __shfl_xor_sync(0xffffffffu, s, o);
        q += __shfl_xor_sync(0xffffffffu, q, o);
    }
    if (lane == 0) {
        g_S1[gwarp] = s;
        g_Q[gwarp] = q;
    }
}

// ---------------------------------------------------------------------------
// Stage B: per-batch scan over T frames. 1 block per batch, 1024 threads,
// 8 frames/thread. Two double-precision prefix sums (S1 then D), producing
// per-frame mean and inv_std.
// ---------------------------------------------------------------------------
__global__ void __launch_bounds__(1024) stageB() {
    __shared__ double sh[1024];
    const int b = blockIdx.x;
    const int tid = threadIdx.x;
    const int EPT = TT / 1024;  // 8
    const int base = b * TT + tid * EPT;

    // --- prefix sum of S1 ---
    double loc[8];
    float s1f[8], qf[8];
    double run = 0.0;
#pragma unroll
    for (int i = 0; i < EPT; i++) {
        s1f[i] = g_S1[base + i];
        qf[i] = g_Q[base + i];
        run += (double)s1f[i];
        loc[i] = run;
    }
    sh[tid] = run;
    __syncthreads();
    // Hillis–Steele inclusive scan over 1024 thread-totals
    for (int off = 1; off < 1024; off <<= 1) {
        double v = sh[tid];
        double add = (tid >= off) ? sh[tid - off] : 0.0;
        __syncthreads();
        sh[tid] = v + add;
        __syncthreads();
    }
    double excl = (tid > 0) ? sh[tid - 1] : 0.0;
    __syncthreads();

    // --- per-frame mean, D; local prefix of D ---
    double dloc[8];
    float means[8];
    double drun = 0.0;
#pragma unroll
    for (int i = 0; i < EPT; i++) {
        int t = tid * EPT + i;
        double P = loc[i] + excl;
        double cnt = (double)(t + 1) * (double)CC;
        double m = P / cnt;
        means[i] = (float)m;
        double s1 = (double)s1f[i];
        double qq = (double)qf[i];
        double D = qq - 2.0 * m * s1 + (double)CC * m * m;
        drun += D;
        dloc[i] = drun;
    }
    sh[tid] = drun;
    __syncthreads();
    for (int off = 1; off < 1024; off <<= 1) {
        double v = sh[tid];
        double add = (tid >= off) ? sh[tid - off] : 0.0;
        __syncthreads();
        sh[tid] = v + add;
        __syncthreads();
    }
    double dexcl = (tid > 0) ? sh[tid - 1] : 0.0;

#pragma unroll
    for (int i = 0; i < EPT; i++) {
        int t = tid * EPT + i;
        double V = dloc[i] + dexcl;
        double cnt = (double)(t + 1) * (double)CC;
        float var = (float)(V / cnt);
        g_mean[base + i] = means[i];
        g_inv[base + i] = rsqrtf(var + EPSF);
    }
}

// ---------------------------------------------------------------------------
// Stage C: elementwise normalize. float4 per thread.
// out = (x - mean[f]) * inv[f] * w[c]
// ---------------------------------------------------------------------------
__global__ void __launch_bounds__(256) stageC(const float* __restrict__ x,
                                              const float* __restrict__ w,
                                              float* __restrict__ out) {
    const size_t i = (size_t)blockIdx.x * blockDim.x + threadIdx.x;  // float4 idx
    const int f = (int)(i >> 7);   // 128 float4 per frame
    const int c4 = (int)(i & 127); // float4 index within channels

    float4 v = reinterpret_cast<const float4*>(x)[i];
    float4 wv = reinterpret_cast<const float4*>(w)[c4];
    float m = g_mean[f];
    float s = g_inv[f];
    float4 o;
    o.x = (v.x - m) * s * wv.x;
    o.y = (v.y - m) * s * wv.y;
    o.z = (v.z - m) * s * wv.z;
    o.w = (v.w - m) * s * wv.w;
    reinterpret_cast<float4*>(out)[i] = o;
}

// ---------------------------------------------------------------------------
extern "C" void kernel_launch(void* const* d_in, const int* in_sizes, int n_in,
                              void* d_out, int out_size) {
    const float* x = (const float*)d_in[0];
    const float* w = (const float*)d_in[1];
    float* out = (float*)d_out;

    // Stage A: B*T frames, one warp each -> B*T*32 threads
    {
        int threads = 256;
        int blocks = (BB * TT * 32) / threads;  // 8192
        stageA<<<blocks, threads>>>(x);
    }
    // Stage B: one block per batch
    stageB<<<BB, 1024>>>();
    // Stage C: B*T*C/4 float4 elements
    {
        int threads = 256;
        int blocks = (BB * TT * CC / 4) / threads;  // 32768
        stageC<<<blocks, threads>>>(x, w, out);
    }
}

// round 2
// speedup vs baseline: 1.8074x; 1.8074x over previous
#include <cuda_runtime.h>

// Shape fixed by setup_inputs: x [8, 8192, 512] fp32, weight [512] fp32.
#define BB 8
#define TT 8192
#define CC 512
#define EPSF 1e-5f

#define THREADS 512              // 16 warps
#define FPB 256                  // frames per block
#define BPB (TT / FPB)           // 32 blocks per batch
#define GRID (BB * BPB)          // 256 blocks total (all resident at 2/SM)
#define FPW (FPB / (THREADS/32)) // 16 frames per warp

// Scratch + sync state (device globals; no allocation allowed).
__device__ float g_aggS1[GRID];
__device__ float g_aggD[GRID];
__device__ int g_cnt1;
__device__ int g_cnt2;

__global__ void initk() { g_cnt1 = 0; g_cnt2 = 0; }

__global__ void __launch_bounds__(THREADS, 2)
fused(const float* __restrict__ x, const float* __restrict__ w,
      float* __restrict__ out) {
    __shared__ float sS1[FPB];   // raw per-frame channel sums
    __shared__ float sQ[FPB];    // raw per-frame sum of squares (later: D)
    __shared__ float sI1[FPB];   // block-inclusive prefix of S1
    __shared__ float sID[FPB];   // block-inclusive prefix of D
    __shared__ float sMean[FPB];
    __shared__ float sInv[FPB];
    __shared__ float sExcl1, sExclD;

    const int b = blockIdx.x / BPB;
    const int kb = blockIdx.x % BPB;
    const int wid = threadIdx.x >> 5;
    const int lane = threadIdx.x & 31;
    const size_t frame0 = (size_t)b * TT + (size_t)kb * FPB;

    // ---------------- Phase 1: per-frame reductions (one warp per frame) ---
    for (int j = 0; j < FPW; j++) {
        const int f = wid * FPW + j;
        const float4* p = reinterpret_cast<const float4*>(x + (frame0 + f) * CC);
        float s = 0.f, q = 0.f;
#pragma unroll
        for (int k = 0; k < 4; k++) {
            float4 v = p[lane + k * 32];
            s += (v.x + v.y) + (v.z + v.w);
            q += v.x * v.x + v.y * v.y + v.z * v.z + v.w * v.w;
        }
#pragma unroll
        for (int o = 16; o > 0; o >>= 1) {
            s += __shfl_xor_sync(0xffffffffu, s, o);
            q += __shfl_xor_sync(0xffffffffu, q, o);
        }
        if (lane == 0) { sS1[f] = s; sQ[f] = q; }
    }
    __syncthreads();

    // ---------------- Block scan of S1 (warp 0, 8 values/lane) -------------
    if (wid == 0) {
        float v[8];
        float run = 0.f;
#pragma unroll
        for (int i = 0; i < 8; i++) { v[i] = sS1[lane * 8 + i]; run += v[i]; v[i] = run; }
        float incl = run;
#pragma unroll
        for (int o = 1; o < 32; o <<= 1) {
            float t = __shfl_up_sync(0xffffffffu, incl, o);
            if (lane >= o) incl += t;
        }
        float excl = incl - run;
#pragma unroll
        for (int i = 0; i < 8; i++) sI1[lane * 8 + i] = v[i] + excl;
        if (lane == 31) g_aggS1[blockIdx.x] = incl;
    }
    __syncthreads();

    // ---------------- Grid barrier 1 (all 256 blocks resident) -------------
    if (threadIdx.x == 0) {
        __threadfence();
        atomicAdd(&g_cnt1, 1);
        while (*(volatile int*)&g_cnt1 < GRID) { __nanosleep(32); }
        __threadfence();
    }
    __syncthreads();

    // Exclusive prefix over predecessor blocks of same batch (kb <= 31)
    if (wid == 0) {
        float v = 0.f;
        if (lane < kb) v = *(volatile float*)&g_aggS1[b * BPB + lane];
#pragma unroll
        for (int o = 16; o > 0; o >>= 1) v += __shfl_xor_sync(0xffffffffu, v, o);
        if (lane == 0) sExcl1 = v;
    }
    __syncthreads();

    // ---------------- Phase 2a: per-frame mean and D -----------------------
    if (threadIdx.x < FPB) {
        const int t = kb * FPB + threadIdx.x;
        const float P = sExcl1 + sI1[threadIdx.x];
        const float cnt = (float)(t + 1) * (float)CC;
        const float m = P / cnt;
        sMean[threadIdx.x] = m;
        const float s1 = sS1[threadIdx.x];
        const float D = sQ[threadIdx.x] - 2.f * m * s1 + (float)CC * m * m;
        sQ[threadIdx.x] = D;  // reuse slot
    }
    __syncthreads();

    // ---------------- Block scan of D (warp 0) -----------------------------
    if (wid == 0) {
        float v[8];
        float run = 0.f;
#pragma unroll
        for (int i = 0; i < 8; i++) { v[i] = sQ[lane * 8 + i]; run += v[i]; v[i] = run; }
        float incl = run;
#pragma unroll
        for (int o = 1; o < 32; o <<= 1) {
            float t = __shfl_up_sync(0xffffffffu, incl, o);
            if (lane >= o) incl += t;
        }
        float excl = incl - run;
#pragma unroll
        for (int i = 0; i < 8; i++) sID[lane * 8 + i] = v[i] + excl;
        if (lane == 31) g_aggD[blockIdx.x] = incl;
    }
    __syncthreads();

    // ---------------- Grid barrier 2 ---------------------------------------
    if (threadIdx.x == 0) {
        __threadfence();
        atomicAdd(&g_cnt2, 1);
        while (*(volatile int*)&g_cnt2 < GRID) { __nanosleep(32); }
        __threadfence();
    }
    __syncthreads();

    if (wid == 0) {
        float v = 0.f;
        if (lane < kb) v = *(volatile float*)&g_aggD[b * BPB + lane];
#pragma unroll
        for (int o = 16; o > 0; o >>= 1) v += __shfl_xor_sync(0xffffffffu, v, o);
        if (lane == 0) sExclD = v;
    }
    __syncthreads();

    if (threadIdx.x < FPB) {
        const int t = kb * FPB + threadIdx.x;
        const float cnt = (float)(t + 1) * (float)CC;
        const float var = (sExclD + sID[threadIdx.x]) / cnt;
        sInv[threadIdx.x] = rsqrtf(var + EPSF);
    }
    __syncthreads();

    // ---------------- Phase 3: normalize (x re-read hits L2) ---------------
    for (int j = 0; j < FPW; j++) {
        const int f = wid * FPW + j;
        const float m = sMean[f];
        const float iv = sInv[f];
        const float4* p = reinterpret_cast<const float4*>(x + (frame0 + f) * CC);
        float4* o = reinterpret_cast<float4*>(out + (frame0 + f) * CC);
        const float4* w4 = reinterpret_cast<const float4*>(w);
#pragma unroll
        for (int k = 0; k < 4; k++) {
            float4 v = p[lane + k * 32];
            float4 wv = w4[lane + k * 32];
            float4 r;
            r.x = (v.x - m) * iv * wv.x;
            r.y = (v.y - m) * iv * wv.y;
            r.z = (v.z - m) * iv * wv.z;
            r.w = (v.w - m) * iv * wv.w;
            o[lane + k * 32] = r;
        }
    }
}

extern "C" void kernel_launch(void* const* d_in, const int* in_sizes, int n_in,
                              void* d_out, int out_size) {
    const float* x = (const float*)d_in[0];
    const float* w = (const float*)d_in[1];
    float* out = (float*)d_out;

    initk<<<1, 1>>>();
    fused<<<GRID, THREADS>>>(x, w, out);
}

// round 3
// speedup vs baseline: 1.8730x; 1.0363x over previous
#include <cuda_runtime.h>

// Shape fixed by setup_inputs: x [8, 8192, 512] fp32, weight [512] fp32.
#define BB 8
#define TT 8192
#define CC 512
#define EPSF 1e-5f

#define THREADS 512              // 16 warps
#define FPB 256                  // frames per block
#define BPB (TT / FPB)           // 32 blocks per batch
#define GRID (BB * BPB)          // 256 blocks total
#define FPW (FPB / (THREADS/32)) // 16 frames per warp

// Published per-block aggregates: low 32 bits = float value, high 32 = flag.
__device__ unsigned long long g_pubS1[GRID];
__device__ unsigned long long g_pubD[GRID];

__global__ void initk() {
    int i = threadIdx.x;
    if (i < GRID) { g_pubS1[i] = 0ull; g_pubD[i] = 0ull; }
}

__device__ __forceinline__ void publish(unsigned long long* slot, float v) {
    unsigned long long u = ((unsigned long long)1u << 32) | (unsigned long long)__float_as_uint(v);
    *(volatile unsigned long long*)slot = u;
}

// Warp 0: sum predecessor aggregates of same batch (lane < kb), spinning on flags.
__device__ __forceinline__ float lookback(unsigned long long* arr, int b, int kb, int lane) {
    float v = 0.f;
    if (lane < kb) {
        unsigned long long u;
        do {
            u = *(volatile unsigned long long*)&arr[b * BPB + lane];
        } while (!(u >> 32));
        v = __uint_as_float((unsigned)u);
    }
#pragma unroll
    for (int o = 16; o > 0; o >>= 1) v += __shfl_xor_sync(0xffffffffu, v, o);
    return v;
}

__global__ void __launch_bounds__(THREADS, 2)
fused(const float* __restrict__ x, const float* __restrict__ w,
      float* __restrict__ out) {
    __shared__ float sS1[FPB];   // raw per-frame channel sums
    __shared__ float sQ[FPB];    // raw per-frame sum of squares (later: D)
    __shared__ float sI1[FPB];   // block-inclusive prefix of S1
    __shared__ float sID[FPB];   // block-inclusive prefix of D
    __shared__ float sMean[FPB];
    __shared__ float sInv[FPB];
    __shared__ float sExcl1, sExclD;

    const int b = blockIdx.x / BPB;
    const int kb = blockIdx.x % BPB;
    const int wid = threadIdx.x >> 5;
    const int lane = threadIdx.x & 31;
    const size_t frame0 = (size_t)b * TT + (size_t)kb * FPB;

    // Weight registers (same 16 floats used for every frame handled by a lane).
    const float4* w4 = reinterpret_cast<const float4*>(w);
    float4 wv[4];
#pragma unroll
    for (int k = 0; k < 4; k++) wv[k] = w4[lane + k * 32];

    // ---------------- Phase 1: per-frame reductions (one warp per frame) ---
    for (int j = 0; j < FPW; j++) {
        const int f = wid * FPW + j;
        const float4* p = reinterpret_cast<const float4*>(x + (frame0 + f) * CC);
        float s = 0.f, q = 0.f;
#pragma unroll
        for (int k = 0; k < 4; k++) {
            float4 v = p[lane + k * 32];
            s += (v.x + v.y) + (v.z + v.w);
            q += v.x * v.x + v.y * v.y + v.z * v.z + v.w * v.w;
        }
#pragma unroll
        for (int o = 16; o > 0; o >>= 1) {
            s += __shfl_xor_sync(0xffffffffu, s, o);
            q += __shfl_xor_sync(0xffffffffu, q, o);
        }
        if (lane == 0) { sS1[f] = s; sQ[f] = q; }
    }
    __syncthreads();

    // ---------------- Block scan of S1 (warp 0, 8 values/lane) + publish ---
    if (wid == 0) {
        float v[8];
        float run = 0.f;
#pragma unroll
        for (int i = 0; i < 8; i++) { v[i] = sS1[lane * 8 + i]; run += v[i]; v[i] = run; }
        float incl = run;
#pragma unroll
        for (int o = 1; o < 32; o <<= 1) {
            float t = __shfl_up_sync(0xffffffffu, incl, o);
            if (lane >= o) incl += t;
        }
        float excl = incl - run;
#pragma unroll
        for (int i = 0; i < 8; i++) sI1[lane * 8 + i] = v[i] + excl;
        if (lane == 31) publish(&g_pubS1[blockIdx.x], incl);
        // Lookback for exclusive prefix over same-batch predecessors.
        float e = lookback(g_pubS1, b, kb, lane);
        if (lane == 0) sExcl1 = e;
    }
    __syncthreads();

    // ---------------- Phase 2a: per-frame mean and D -----------------------
    if (threadIdx.x < FPB) {
        const int t = kb * FPB + threadIdx.x;
        const float P = sExcl1 + sI1[threadIdx.x];
        const float cnt = (float)(t + 1) * (float)CC;
        const float m = P / cnt;
        sMean[threadIdx.x] = m;
        const float s1 = sS1[threadIdx.x];
        const float D = sQ[threadIdx.x] - 2.f * m * s1 + (float)CC * m * m;
        sQ[threadIdx.x] = D;  // reuse slot
    }
    __syncthreads();

    // ---------------- Block scan of D (warp 0) + publish + lookback --------
    if (wid == 0) {
        float v[8];
        float run = 0.f;
#pragma unroll
        for (int i = 0; i < 8; i++) { v[i] = sQ[lane * 8 + i]; run += v[i]; v[i] = run; }
        float incl = run;
#pragma unroll
        for (int o = 1; o < 32; o <<= 1) {
            float t = __shfl_up_sync(0xffffffffu, incl, o);
            if (lane >= o) incl += t;
        }
        float excl = incl - run;
#pragma unroll
        for (int i = 0; i < 8; i++) sID[lane * 8 + i] = v[i] + excl;
        if (lane == 31) publish(&g_pubD[blockIdx.x], incl);
        float e = lookback(g_pubD, b, kb, lane);
        if (lane == 0) sExclD = e;
    }
    __syncthreads();

    if (threadIdx.x < FPB) {
        const int t = kb * FPB + threadIdx.x;
        const float cnt = (float)(t + 1) * (float)CC;
        const float var = (sExclD + sID[threadIdx.x]) / cnt;
        sInv[threadIdx.x] = rsqrtf(var + EPSF);
    }
    __syncthreads();

    // ---------------- Phase 3: normalize (re-read is L1/L2-hot) ------------
    for (int j = 0; j < FPW; j++) {
        const int f = wid * FPW + j;
        const float m = sMean[f];
        const float iv = sInv[f];
        const float4* p = reinterpret_cast<const float4*>(x + (frame0 + f) * CC);
        float4* o = reinterpret_cast<float4*>(out + (frame0 + f) * CC);
#pragma unroll
        for (int k = 0; k < 4; k++) {
            float4 v = p[lane + k * 32];
            float4 r;
            r.x = (v.x - m) * iv * wv[k].x;
            r.y = (v.y - m) * iv * wv[k].y;
            r.z = (v.z - m) * iv * wv[k].z;
            r.w = (v.w - m) * iv * wv[k].w;
            __stcs(&o[lane + k * 32], r);  // streaming store: don't pollute L2
        }
    }
}

extern "C" void kernel_launch(void* const* d_in, const int* in_sizes, int n_in,
                              void* d_out, int out_size) {
    const float* x = (const float*)d_in[0];
    const float* w = (const float*)d_in[1];
    float* out = (float*)d_out;

    initk<<<1, 256>>>();
    fused<<<GRID, THREADS>>>(x, w, out);
}